// round 8
// baseline (speedup 1.0000x reference)
#include <cuda_runtime.h>
#include <cuda_bf16.h>
#include <cuda_fp16.h>
#include <cuda_fp8.h>
#include <cstdint>
#include <cstddef>

#define B_ROWS 4096
#define DDIM   512
#define KN     16384
#define EPSV   1e-6f
#define DELTA  32.0f

// ---------------- device scratch (no allocation allowed) ----------------
__device__ unsigned char gX8[(size_t)B_ROWS * DDIM];   // X e4m3 row-major (b,d)
__device__ unsigned char gW8t[(size_t)KN * DDIM];      // W^T e4m3 row-major (n,d)
__device__ float         gWt32[(size_t)KN * DDIM];     // W^T fp32 (n,d) for refine
__device__ __half        g_d2h[(size_t)B_ROWS * KN];   // approx d2 (fp16)
__device__ float         g_c[KN];                      // exact col stats
__device__ float         g_r[B_ROWS];                  // exact row stats
__device__ unsigned      g_amin[B_ROWS];               // approx row min (float bits)
__device__ float         g_dist[B_ROWS];               // per-row exact min dist

// ---------------- helpers ----------------
__device__ __forceinline__ uint32_t smem_u32(const void* p) {
    uint32_t a;
    asm("{ .reg .u64 t; cvta.to.shared.u64 t, %1; cvt.u32.u64 %0, t; }" : "=r"(a) : "l"(p));
    return a;
}
__device__ __forceinline__ void cpa16(uint32_t dst, const void* src) {
    asm volatile("cp.async.cg.shared.global [%0], [%1], 16;\n" :: "r"(dst), "l"(src));
}
#define CP_COMMIT() asm volatile("cp.async.commit_group;\n" ::: "memory")
#define CP_WAIT(n)  asm volatile("cp.async.wait_group %0;\n" :: "n"(n) : "memory")

__device__ __forceinline__ void ldsm_x4(uint32_t addr, uint32_t r[4]) {
    asm volatile("ldmatrix.sync.aligned.m8n8.x4.shared.b16 {%0,%1,%2,%3}, [%4];"
        : "=r"(r[0]), "=r"(r[1]), "=r"(r[2]), "=r"(r[3]) : "r"(addr));
}
// fp8 e4m3 MMA: D[16x8] += A[16x32] * B[32x8], fp32 accum (sm_89+ plain PTX)
__device__ __forceinline__ void mma_fp8(float c[4], const uint32_t a[4],
                                        uint32_t b0, uint32_t b1) {
    asm volatile("mma.sync.aligned.m16n8k32.row.col.f32.e4m3.e4m3.f32 "
        "{%0,%1,%2,%3}, {%4,%5,%6,%7}, {%8,%9}, {%0,%1,%2,%3};"
        : "+f"(c[0]), "+f"(c[1]), "+f"(c[2]), "+f"(c[3])
        : "r"(a[0]), "r"(a[1]), "r"(a[2]), "r"(a[3]), "r"(b0), "r"(b1));
}

// ---------------- prep kernels ----------------
__global__ void init_kernel() {
    int i = blockIdx.x * blockDim.x + threadIdx.x;
    if (i < B_ROWS) g_amin[i] = 0x7F800000u;  // +inf
}

__global__ void convx_kernel(const float* __restrict__ X) {
    int i = blockIdx.x * blockDim.x + threadIdx.x;
    if (i >= B_ROWS * DDIM / 2) return;
    float2 v = ((const float2*)X)[i];
    ((__nv_fp8x2_storage_t*)gX8)[i] =
        __nv_cvt_float2_to_fp8x2(v, __NV_SATFINITE, __NV_E4M3);
}

__global__ void transw_kernel(const float* __restrict__ W) {
    __shared__ float t[32][33];
    int x = blockIdx.x * 32 + threadIdx.x;  // n
    int y = blockIdx.y * 32 + threadIdx.y;  // d
    #pragma unroll
    for (int j = 0; j < 32; j += 8)
        t[threadIdx.y + j][threadIdx.x] = W[(size_t)(y + j) * KN + x];
    __syncthreads();
    int nx = blockIdx.y * 32 + threadIdx.x;  // d
    int ny = blockIdx.x * 32 + threadIdx.y;  // n
    #pragma unroll
    for (int j = 0; j < 32; j += 8) {
        float v = t[threadIdx.x][threadIdx.y + j];
        gWt32[(size_t)(ny + j) * DDIM + nx] = v;
        gW8t[(size_t)(ny + j) * DDIM + nx] =
            __nv_cvt_float_to_fp8(v, __NV_SATFINITE, __NV_E4M3);
    }
}

// warp per column, reads transposed fp32 copy (contiguous, L2-hot)
__global__ void col_stats_kernel() {
    int gw = (blockIdx.x * blockDim.x + threadIdx.x) >> 5;
    int lane = threadIdx.x & 31;
    if (gw >= KN) return;
    const float4* p = (const float4*)(gWt32 + (size_t)gw * DDIM);
    float s = 0.f, s2 = 0.f;
    #pragma unroll
    for (int i = 0; i < 4; ++i) {
        float4 v = p[i * 32 + lane];
        s += v.x + v.y + v.z + v.w;
        s2 = fmaf(v.x, v.x, s2); s2 = fmaf(v.y, v.y, s2);
        s2 = fmaf(v.z, v.z, s2); s2 = fmaf(v.w, v.w, s2);
    }
    #pragma unroll
    for (int o = 16; o; o >>= 1) {
        s  += __shfl_xor_sync(0xFFFFFFFFu, s,  o);
        s2 += __shfl_xor_sync(0xFFFFFFFFu, s2, o);
    }
    if (lane == 0) g_c[gw] = s2 - 2.f * EPSV * s;
}

__global__ void row_stats_kernel(const float* __restrict__ X) {
    int b = blockIdx.x, t = threadIdx.x;
    float4 v = ((const float4*)(X + (size_t)b * DDIM))[t];
    float s = v.x + v.y + v.z + v.w;
    float s2 = v.x * v.x + v.y * v.y + v.z * v.z + v.w * v.w;
    #pragma unroll
    for (int o = 16; o; o >>= 1) {
        s  += __shfl_xor_sync(0xFFFFFFFFu, s,  o);
        s2 += __shfl_xor_sync(0xFFFFFFFFu, s2, o);
    }
    __shared__ float sh[8];
    int w = t >> 5;
    if ((t & 31) == 0) { sh[w] = s; sh[4 + w] = s2; }
    __syncthreads();
    if (t == 0) {
        float S = sh[0] + sh[1] + sh[2] + sh[3];
        float S2 = sh[4] + sh[5] + sh[6] + sh[7];
        g_r[b] = S2 + 2.f * EPSV * S + (float)DDIM * EPSV * EPSV;
    }
}

// -------- fp8 mma.sync GEMM, 128x128 tile, Kc=128 (128B rows), dbl-buffered --
//   0    : sCol (128 f32)
//   512  : sRow (128 f32)
//   1024 : sRowMin (128 u32)
//   2048 : A0 16KB / A1 / B0 / B1   (reused post-loop as d2 staging, stride 272B)
#define SM_COL   0
#define SM_ROW   512
#define SM_RMIN  1024
#define SM_A0    2048
#define SM_A1    18432
#define SM_B0    34816
#define SM_B1    51200
#define SM_STG   2048
#define STG_STRIDE 272
#define SMEM_TOT 67584
#define NCHUNK   4   // 512 / 128

__global__ void __launch_bounds__(256)
gemm_kernel() {
    extern __shared__ char smem[];
    const uint32_t sb = smem_u32(smem);
    const int tid  = threadIdx.x;
    const int wid  = tid >> 5;
    const int lane = tid & 31;
    const int wm = wid >> 2;        // 0..1  (64 rows each)
    const int wn = wid & 3;         // 0..3  (32 cols each)
    const int rowBase = blockIdx.y * 128;
    const int colBase = blockIdx.x * 128;

    float*    sCol  = (float*)(smem + SM_COL);
    float*    sRow  = (float*)(smem + SM_ROW);
    unsigned* sRMin = (unsigned*)(smem + SM_RMIN);

    if (tid < 128) {
        sCol[tid]  = g_c[colBase + tid];
        sRow[tid]  = g_r[rowBase + tid];
        sRMin[tid] = 0x7F800000u;
    }

    const uint32_t offA[2] = {SM_A0, SM_A1};
    const uint32_t offB[2] = {SM_B0, SM_B1};

    auto load_chunk = [&](int c) {
        const int buf = c & 1;
        const char* As = (const char*)gX8 + (size_t)rowBase * DDIM + c * 128;
        const char* Bs = (const char*)gW8t + (size_t)colBase * DDIM + c * 128;
        #pragma unroll
        for (int i = 0; i < 4; ++i) {   // A: 1024 granules of 16B
            int g = tid + i * 256;
            int r = g >> 3, gi = g & 7;
            uint32_t d = r * 128 + ((gi * 16) ^ ((r & 7) << 4));
            cpa16(sb + offA[buf] + d, As + (size_t)r * DDIM + gi * 16);
        }
        #pragma unroll
        for (int i = 0; i < 4; ++i) {   // B: 1024 granules
            int g = tid + i * 256;
            int n = g >> 3, gi = g & 7;
            uint32_t d = n * 128 + ((gi * 16) ^ ((n & 7) << 4));
            cpa16(sb + offB[buf] + d, Bs + (size_t)n * DDIM + gi * 16);
        }
        CP_COMMIT();
    };

    // ldmatrix addressing: byte-identical to bf16 version (rows are 128B)
    uint32_t baseA[4], patA[4];
    #pragma unroll
    for (int mi = 0; mi < 4; ++mi) {
        int r = wm * 64 + mi * 16 + (lane & 15);
        baseA[mi] = r * 128;
        patA[mi]  = (r & 7) << 4;
    }
    const uint32_t aQuad = (lane >> 4) * 16;
    uint32_t baseB[2], patB[2];
    #pragma unroll
    for (int bi = 0; bi < 2; ++bi) {
        int n = wn * 32 + bi * 16 + (lane & 7) + ((lane >> 4) << 3);
        baseB[bi] = n * 128;
        patB[bi]  = (n & 7) << 4;
    }
    const uint32_t bQuad = ((lane >> 3) & 1) * 16;

    float acc[4][4][4];
    #pragma unroll
    for (int a = 0; a < 4; ++a)
        #pragma unroll
        for (int b = 0; b < 4; ++b)
            #pragma unroll
            for (int q = 0; q < 4; ++q) acc[a][b][q] = 0.f;

    load_chunk(0);

    for (int c = 0; c < NCHUNK; ++c) {
        if (c + 1 < NCHUNK) { load_chunk(c + 1); CP_WAIT(1); }
        else                { CP_WAIT(0); }
        __syncthreads();

        const uint32_t aBuf = sb + offA[c & 1];
        const uint32_t bBuf = sb + offB[c & 1];
        #pragma unroll
        for (int kk = 0; kk < 4; ++kk) {    // 4 x 32B = 128 fp8 k-slices
            const uint32_t kb = kk * 32;
            uint32_t af[4][4], bf[2][4];
            #pragma unroll
            for (int mi = 0; mi < 4; ++mi)
                ldsm_x4(aBuf + baseA[mi] + ((kb + aQuad) ^ patA[mi]), af[mi]);
            #pragma unroll
            for (int bi = 0; bi < 2; ++bi)
                ldsm_x4(bBuf + baseB[bi] + ((kb + bQuad) ^ patB[bi]), bf[bi]);
            #pragma unroll
            for (int mi = 0; mi < 4; ++mi)
                #pragma unroll
                for (int bi = 0; bi < 2; ++bi) {
                    mma_fp8(acc[mi][bi * 2 + 0], af[mi], bf[bi][0], bf[bi][1]);
                    mma_fp8(acc[mi][bi * 2 + 1], af[mi], bf[bi][2], bf[bi][3]);
                }
        }
        __syncthreads();
    }

    // ---- epilogue: d2 -> smem staging (coalesced writeback) + row-min ----
    const int g   = lane >> 2;
    const int tig = lane & 3;
    #pragma unroll
    for (int mi = 0; mi < 4; ++mi) {
        const int r0 = wm * 64 + mi * 16 + g;
        const int r1 = r0 + 8;
        const float rr0 = sRow[r0], rr1 = sRow[r1];
        unsigned m0 = 0x7F800000u, m1 = 0x7F800000u;
        #pragma unroll
        for (int j = 0; j < 4; ++j) {
            const int cb = wn * 32 + j * 8 + 2 * tig;
            const float cc0 = sCol[cb], cc1 = sCol[cb + 1];
            float d00 = rr0 + cc0 - 2.f * acc[mi][j][0];
            float d01 = rr0 + cc1 - 2.f * acc[mi][j][1];
            float d10 = rr1 + cc0 - 2.f * acc[mi][j][2];
            float d11 = rr1 + cc1 - 2.f * acc[mi][j][3];
            __half2 h0 = __floats2half2_rn(d00, d01);
            __half2 h1 = __floats2half2_rn(d10, d11);
            *(__half2*)(smem + SM_STG + r0 * STG_STRIDE + cb * 2) = h0;
            *(__half2*)(smem + SM_STG + r1 * STG_STRIDE + cb * 2) = h1;
            m0 = min(m0, min(__float_as_uint(__low2float(h0)),
                             __float_as_uint(__high2float(h0))));
            m1 = min(m1, min(__float_as_uint(__low2float(h1)),
                             __float_as_uint(__high2float(h1))));
        }
        #pragma unroll
        for (int o = 1; o < 4; o <<= 1) {
            m0 = min(m0, __shfl_xor_sync(0xFFFFFFFFu, m0, o));
            m1 = min(m1, __shfl_xor_sync(0xFFFFFFFFu, m1, o));
        }
        if (tig == 0) {
            atomicMin(&sRMin[r0], m0);
            atomicMin(&sRMin[r1], m1);
        }
    }
    __syncthreads();
    #pragma unroll
    for (int i = 0; i < 8; ++i) {   // coalesced 16B writeback
        int ch = tid + i * 256;
        int row = ch >> 4, ci = ch & 15;
        uint4 v = *(const uint4*)(smem + SM_STG + row * STG_STRIDE + ci * 16);
        *(uint4*)(g_d2h + (size_t)(rowBase + row) * KN + colBase + ci * 8) = v;
    }
    if (tid < 128) atomicMin(&g_amin[rowBase + tid], sRMin[tid]);
}

// ---------------- refine: shortlist + exact fp32 warp-dot ----------------
__global__ void refine_kernel(const float* __restrict__ X,
                              const float* __restrict__ loc,
                              float* __restrict__ out, int out_size) {
    const int b = blockIdx.x;
    const int tid = threadIdx.x;
    const int wid = tid >> 5;
    const int lane = tid & 31;
    __shared__ int cnt;
    __shared__ int cand[2048];
    __shared__ unsigned long long wbest[8];
    if (tid == 0) cnt = 0;
    __syncthreads();

    const float thr = __uint_as_float(g_amin[b]) + DELTA;
    const uint4* dp = (const uint4*)(g_d2h + (size_t)b * KN);
    for (int i = tid; i < KN / 8; i += 256) {
        uint4 v = dp[i];
        const uint32_t ww[4] = {v.x, v.y, v.z, v.w};
        #pragma unroll
        for (int q = 0; q < 4; ++q) {
            __half2 h = *(const __half2*)&ww[q];
            if (__low2float(h) <= thr)  { int p = atomicAdd(&cnt, 1); if (p < 2048) cand[p] = i * 8 + 2 * q; }
            if (__high2float(h) <= thr) { int p = atomicAdd(&cnt, 1); if (p < 2048) cand[p] = i * 8 + 2 * q + 1; }
        }
    }
    __syncthreads();
    const int n = min(cnt, 2048);

    const float4* xr = (const float4*)(X + (size_t)b * DDIM);
    float4 xv[4];
    #pragma unroll
    for (int i = 0; i < 4; ++i) xv[i] = xr[i * 32 + lane];

    unsigned long long best = 0xFFFFFFFFFFFFFFFFULL;
    for (int ci = wid; ci < n; ci += 8) {
        const int k = cand[ci];
        const float4* wr = (const float4*)(gWt32 + (size_t)k * DDIM);
        float s = 0.f;
        #pragma unroll
        for (int i = 0; i < 4; ++i) {
            float4 w = wr[i * 32 + lane];
            s = fmaf(xv[i].x, w.x, s);
            s = fmaf(xv[i].y, w.y, s);
            s = fmaf(xv[i].z, w.z, s);
            s = fmaf(xv[i].w, w.w, s);
        }
        #pragma unroll
        for (int o = 16; o; o >>= 1) s += __shfl_xor_sync(0xFFFFFFFFu, s, o);
        if (lane == 0) {
            float d2 = g_r[b] + g_c[k] - 2.f * s;
            unsigned u = __float_as_uint(d2);
            u = (u & 0x80000000u) ? ~u : (u | 0x80000000u);
            unsigned long long key = ((unsigned long long)u << 32) | (unsigned)k;
            if (key < best) best = key;
        }
    }
    if (lane == 0) wbest[wid] = best;
    __syncthreads();

    if (tid == 0) {
        unsigned long long bb = 0xFFFFFFFFFFFFFFFFULL;
        #pragma unroll
        for (int w = 0; w < 8; ++w) if (wbest[w] < bb) bb = wbest[w];
        unsigned k = (unsigned)(bb & 0xFFFFFFFFu);
        unsigned u = (unsigned)(bb >> 32);
        u = (u & 0x80000000u) ? (u & 0x7FFFFFFFu) : ~u;
        float d2 = __uint_as_float(u);
        g_dist[b] = sqrtf(fmaxf(d2, 0.f));
        out[2 * b] = loc[2 * k];
        if (2 * b + 1 < out_size - 1) out[2 * b + 1] = loc[2 * k + 1];
    }
}

__global__ void loss_kernel(float* __restrict__ out, int out_size) {
    __shared__ float sh[1024];
    float local = 0.f;
    for (int b = threadIdx.x; b < B_ROWS; b += 1024) local += g_dist[b];
    sh[threadIdx.x] = local;
    __syncthreads();
    #pragma unroll
    for (int s = 512; s > 0; s >>= 1) {
        if (threadIdx.x < s) sh[threadIdx.x] += sh[threadIdx.x + s];
        __syncthreads();
    }
    if (threadIdx.x == 0) out[out_size - 1] = sh[0] / (float)B_ROWS;
}

// ---------------------------------------------------------------------------
extern "C" void kernel_launch(void* const* d_in, const int* in_sizes, int n_in,
                              void* d_out, int out_size) {
    const float* X = (const float*)d_in[0];  // (4096, 512)
    const float* W = (const float*)d_in[1];  // (512, 16384)
    const float* L = (const float*)d_in[2];  // (16384, 2)
    float* out = (float*)d_out;

    cudaFuncSetAttribute(gemm_kernel, cudaFuncAttributeMaxDynamicSharedMemorySize, SMEM_TOT);

    init_kernel<<<(B_ROWS + 255) / 256, 256>>>();
    convx_kernel<<<(B_ROWS * DDIM / 2 + 255) / 256, 256>>>(X);
    transw_kernel<<<dim3(KN / 32, DDIM / 32), dim3(32, 8)>>>(W);
    col_stats_kernel<<<KN * 32 / 256, 256>>>();
    row_stats_kernel<<<B_ROWS, 128>>>(X);

    gemm_kernel<<<dim3(KN / 128, B_ROWS / 128), 256, SMEM_TOT>>>();

    refine_kernel<<<B_ROWS, 256>>>(X, L, out, out_size);
    loss_kernel<<<1, 1024>>>(out, out_size);
}

// round 9
// speedup vs baseline: 1.4504x; 1.4504x over previous
#include <cuda_runtime.h>
#include <cuda_bf16.h>
#include <cuda_fp16.h>
#include <cstdint>
#include <cstddef>

#define B_ROWS 4096
#define DDIM   512
#define KN     16384
#define NGRP   (KN / 8)      // 2048 8-col groups per row
#define EPSV   1e-6f
#define DELTA  4.0f

// ---------------- device scratch (no allocation allowed) ----------------
__device__ __nv_bfloat16 gXb[(size_t)B_ROWS * DDIM];   // X bf16 row-major (b,d)
__device__ __nv_bfloat16 gWt[(size_t)KN * DDIM];       // W^T bf16 row-major (n,d)
__device__ float         gWt32[(size_t)KN * DDIM];     // W^T fp32 (n,d) for refine
__device__ __half        gGmin[(size_t)B_ROWS * NGRP]; // per-(row, 8col-group) d2 min
__device__ float         g_c[KN];                      // exact col stats
__device__ float         g_r[B_ROWS];                  // exact row stats
__device__ float         g_dist[B_ROWS];               // per-row exact min dist

// ---------------- helpers ----------------
__device__ __forceinline__ uint32_t smem_u32(const void* p) {
    uint32_t a;
    asm("{ .reg .u64 t; cvta.to.shared.u64 t, %1; cvt.u32.u64 %0, t; }" : "=r"(a) : "l"(p));
    return a;
}
__device__ __forceinline__ void cpa16(uint32_t dst, const void* src) {
    asm volatile("cp.async.cg.shared.global [%0], [%1], 16;\n" :: "r"(dst), "l"(src));
}
#define CP_COMMIT() asm volatile("cp.async.commit_group;\n" ::: "memory")
#define CP_WAIT(n)  asm volatile("cp.async.wait_group %0;\n" :: "n"(n) : "memory")

__device__ __forceinline__ void ldsm_x4(uint32_t addr, uint32_t r[4]) {
    asm volatile("ldmatrix.sync.aligned.m8n8.x4.shared.b16 {%0,%1,%2,%3}, [%4];"
        : "=r"(r[0]), "=r"(r[1]), "=r"(r[2]), "=r"(r[3]) : "r"(addr));
}
__device__ __forceinline__ void mma_bf16(float c[4], const uint32_t a[4],
                                         uint32_t b0, uint32_t b1) {
    asm volatile("mma.sync.aligned.m16n8k16.row.col.f32.bf16.bf16.f32 "
        "{%0,%1,%2,%3}, {%4,%5,%6,%7}, {%8,%9}, {%0,%1,%2,%3};"
        : "+f"(c[0]), "+f"(c[1]), "+f"(c[2]), "+f"(c[3])
        : "r"(a[0]), "r"(a[1]), "r"(a[2]), "r"(a[3]), "r"(b0), "r"(b1));
}

// ---------------- prep kernels ----------------
__global__ void convx_kernel(const float* __restrict__ X) {
    int i = blockIdx.x * blockDim.x + threadIdx.x;
    if (i < B_ROWS * DDIM) gXb[i] = __float2bfloat16(X[i]);
}

__global__ void transw_kernel(const float* __restrict__ W) {
    __shared__ float t[32][33];
    int x = blockIdx.x * 32 + threadIdx.x;  // n
    int y = blockIdx.y * 32 + threadIdx.y;  // d
    #pragma unroll
    for (int j = 0; j < 32; j += 8)
        t[threadIdx.y + j][threadIdx.x] = W[(size_t)(y + j) * KN + x];
    __syncthreads();
    int nx = blockIdx.y * 32 + threadIdx.x;  // d
    int ny = blockIdx.x * 32 + threadIdx.y;  // n
    #pragma unroll
    for (int j = 0; j < 32; j += 8) {
        float v = t[threadIdx.x][threadIdx.y + j];
        gWt32[(size_t)(ny + j) * DDIM + nx] = v;
        gWt[(size_t)(ny + j) * DDIM + nx] = __float2bfloat16(v);
    }
}

// warp per column, reads transposed fp32 copy (contiguous, L2-hot)
__global__ void col_stats_kernel() {
    int gw = (blockIdx.x * blockDim.x + threadIdx.x) >> 5;
    int lane = threadIdx.x & 31;
    if (gw >= KN) return;
    const float4* p = (const float4*)(gWt32 + (size_t)gw * DDIM);
    float s = 0.f, s2 = 0.f;
    #pragma unroll
    for (int i = 0; i < 4; ++i) {
        float4 v = p[i * 32 + lane];
        s += v.x + v.y + v.z + v.w;
        s2 = fmaf(v.x, v.x, s2); s2 = fmaf(v.y, v.y, s2);
        s2 = fmaf(v.z, v.z, s2); s2 = fmaf(v.w, v.w, s2);
    }
    #pragma unroll
    for (int o = 16; o; o >>= 1) {
        s  += __shfl_xor_sync(0xFFFFFFFFu, s,  o);
        s2 += __shfl_xor_sync(0xFFFFFFFFu, s2, o);
    }
    if (lane == 0) g_c[gw] = s2 - 2.f * EPSV * s;
}

__global__ void row_stats_kernel(const float* __restrict__ X) {
    int b = blockIdx.x, t = threadIdx.x;
    float4 v = ((const float4*)(X + (size_t)b * DDIM))[t];
    float s = v.x + v.y + v.z + v.w;
    float s2 = v.x * v.x + v.y * v.y + v.z * v.z + v.w * v.w;
    #pragma unroll
    for (int o = 16; o; o >>= 1) {
        s  += __shfl_xor_sync(0xFFFFFFFFu, s,  o);
        s2 += __shfl_xor_sync(0xFFFFFFFFu, s2, o);
    }
    __shared__ float sh[8];
    int w = t >> 5;
    if ((t & 31) == 0) { sh[w] = s; sh[4 + w] = s2; }
    __syncthreads();
    if (t == 0) {
        float S = sh[0] + sh[1] + sh[2] + sh[3];
        float S2 = sh[4] + sh[5] + sh[6] + sh[7];
        g_r[b] = S2 + 2.f * EPSV * S + (float)DDIM * EPSV * EPSV;
    }
}

// ---------------- bf16 mma.sync GEMM, 128x128 tile, Kc=64, double-buffered ----
#define SM_COL   0
#define SM_ROW   512
#define SM_A0    2048
#define SM_A1    18432
#define SM_B0    34816
#define SM_B1    51200
#define SMEM_TOT 67584

__global__ void __launch_bounds__(256)
gemm_kernel() {
    extern __shared__ char smem[];
    const uint32_t sb = smem_u32(smem);
    const int tid  = threadIdx.x;
    const int wid  = tid >> 5;
    const int lane = tid & 31;
    const int wm = wid >> 2;        // 0..1  (64 rows each)
    const int wn = wid & 3;         // 0..3  (32 cols each)
    const int rowBase = blockIdx.y * 128;
    const int colBase = blockIdx.x * 128;

    float* sCol = (float*)(smem + SM_COL);
    float* sRow = (float*)(smem + SM_ROW);

    if (tid < 128) {
        sCol[tid] = g_c[colBase + tid];
        sRow[tid] = g_r[rowBase + tid];
    }

    const uint32_t offA[2] = {SM_A0, SM_A1};
    const uint32_t offB[2] = {SM_B0, SM_B1};

    auto load_chunk = [&](int c) {
        const int buf = c & 1;
        const char* As = (const char*)(gXb + (size_t)rowBase * DDIM) + c * 128;
        const char* Bs = (const char*)(gWt + (size_t)colBase * DDIM) + c * 128;
        #pragma unroll
        for (int i = 0; i < 4; ++i) {
            int g = tid + i * 256;
            int r = g >> 3, gi = g & 7;
            uint32_t d = r * 128 + ((gi * 16) ^ ((r & 7) << 4));
            cpa16(sb + offA[buf] + d, As + (size_t)r * 1024 + gi * 16);
        }
        #pragma unroll
        for (int i = 0; i < 4; ++i) {
            int g = tid + i * 256;
            int n = g >> 3, gi = g & 7;
            uint32_t d = n * 128 + ((gi * 16) ^ ((n & 7) << 4));
            cpa16(sb + offB[buf] + d, Bs + (size_t)n * 1024 + gi * 16);
        }
        CP_COMMIT();
    };

    uint32_t baseA[4], patA[4];
    #pragma unroll
    for (int mi = 0; mi < 4; ++mi) {
        int r = wm * 64 + mi * 16 + (lane & 15);
        baseA[mi] = r * 128;
        patA[mi]  = (r & 7) << 4;
    }
    const uint32_t aQuad = (lane >> 4) * 16;
    uint32_t baseB[2], patB[2];
    #pragma unroll
    for (int bi = 0; bi < 2; ++bi) {
        int n = wn * 32 + bi * 16 + (lane & 7) + ((lane >> 4) << 3);
        baseB[bi] = n * 128;
        patB[bi]  = (n & 7) << 4;
    }
    const uint32_t bQuad = ((lane >> 3) & 1) * 16;

    float acc[4][4][4];
    #pragma unroll
    for (int a = 0; a < 4; ++a)
        #pragma unroll
        for (int b = 0; b < 4; ++b)
            #pragma unroll
            for (int q = 0; q < 4; ++q) acc[a][b][q] = 0.f;

    load_chunk(0);

    for (int c = 0; c < 8; ++c) {
        if (c + 1 < 8) { load_chunk(c + 1); CP_WAIT(1); }
        else           { CP_WAIT(0); }
        __syncthreads();

        const uint32_t aBuf = sb + offA[c & 1];
        const uint32_t bBuf = sb + offB[c & 1];
        #pragma unroll
        for (int kk = 0; kk < 4; ++kk) {
            const uint32_t kb = kk * 32;
            uint32_t af[4][4], bf[2][4];
            #pragma unroll
            for (int mi = 0; mi < 4; ++mi)
                ldsm_x4(aBuf + baseA[mi] + ((kb + aQuad) ^ patA[mi]), af[mi]);
            #pragma unroll
            for (int bi = 0; bi < 2; ++bi)
                ldsm_x4(bBuf + baseB[bi] + ((kb + bQuad) ^ patB[bi]), bf[bi]);
            #pragma unroll
            for (int mi = 0; mi < 4; ++mi)
                #pragma unroll
                for (int bi = 0; bi < 2; ++bi) {
                    mma_bf16(acc[mi][bi * 2 + 0], af[mi], bf[bi][0], bf[bi][1]);
                    mma_bf16(acc[mi][bi * 2 + 1], af[mi], bf[bi][2], bf[bi][3]);
                }
        }
        __syncthreads();
    }

    // ---- epilogue: per-(row, 8col-group) d2 mins -> gGmin (16MB total) ----
    // lanes: g = lane>>2 selects row-in-8, tig = lane&3 selects col pair.
    const int tig = lane & 3;
    const int g   = lane >> 2;
    float gm0[4][4], gm1[4][4];
    #pragma unroll
    for (int mi = 0; mi < 4; ++mi) {
        const int r0 = wm * 64 + mi * 16 + g;
        const int r1 = r0 + 8;
        const float rr0 = sRow[r0], rr1 = sRow[r1];
        #pragma unroll
        for (int j = 0; j < 4; ++j) {
            const int cb = wn * 32 + j * 8 + 2 * tig;
            const float cc0 = sCol[cb], cc1 = sCol[cb + 1];
            float m0 = fminf(rr0 + cc0 - 2.f * acc[mi][j][0],
                             rr0 + cc1 - 2.f * acc[mi][j][1]);
            float m1 = fminf(rr1 + cc0 - 2.f * acc[mi][j][2],
                             rr1 + cc1 - 2.f * acc[mi][j][3]);
            // butterfly over the 4 tig lanes -> 8-col group min (all lanes get it)
            m0 = fminf(m0, __shfl_xor_sync(0xFFFFFFFFu, m0, 1));
            m0 = fminf(m0, __shfl_xor_sync(0xFFFFFFFFu, m0, 2));
            m1 = fminf(m1, __shfl_xor_sync(0xFFFFFFFFu, m1, 1));
            m1 = fminf(m1, __shfl_xor_sync(0xFFFFFFFFu, m1, 2));
            gm0[mi][j] = m0;
            gm1[mi][j] = m1;
        }
    }
    if (tig == 0) {
        const int gcol = blockIdx.x * 16 + wn * 4;  // global group index base
        #pragma unroll
        for (int mi = 0; mi < 4; ++mi) {
            const int r0 = rowBase + wm * 64 + mi * 16 + g;
            const int r1 = r0 + 8;
            __half2 a0 = __floats2half2_rn(gm0[mi][0], gm0[mi][1]);
            __half2 a1 = __floats2half2_rn(gm0[mi][2], gm0[mi][3]);
            __half2 b0 = __floats2half2_rn(gm1[mi][0], gm1[mi][1]);
            __half2 b1 = __floats2half2_rn(gm1[mi][2], gm1[mi][3]);
            uint2 v0, v1;
            v0.x = *(uint32_t*)&a0; v0.y = *(uint32_t*)&a1;
            v1.x = *(uint32_t*)&b0; v1.y = *(uint32_t*)&b1;
            *(uint2*)(gGmin + (size_t)r0 * NGRP + gcol) = v0;
            *(uint2*)(gGmin + (size_t)r1 * NGRP + gcol) = v1;
        }
    }
}

// ------- refine: group-min scan -> qualifying groups -> exact fp32 dots -------
__global__ void refine_kernel(const float* __restrict__ X,
                              const float* __restrict__ loc,
                              float* __restrict__ out, int out_size) {
    const int b = blockIdx.x;
    const int tid = threadIdx.x;
    const int wid = tid >> 5;
    const int lane = tid & 31;
    __shared__ unsigned sMin;
    __shared__ int cnt;
    __shared__ int grp[256];
    __shared__ unsigned long long wbest[8];
    if (tid == 0) { sMin = 0x7F800000u; cnt = 0; }
    __syncthreads();

    // each thread loads 8 group-mins (one uint4 = 16B)
    const uint4 v = ((const uint4*)(gGmin + (size_t)b * NGRP))[tid];
    const uint32_t ww[4] = {v.x, v.y, v.z, v.w};
    float h[8];
    #pragma unroll
    for (int q = 0; q < 4; ++q) {
        __half2 p = *(const __half2*)&ww[q];
        h[2 * q]     = __low2float(p);
        h[2 * q + 1] = __high2float(p);
    }
    float m = h[0];
    #pragma unroll
    for (int q = 1; q < 8; ++q) m = fminf(m, h[q]);
    #pragma unroll
    for (int o = 16; o; o >>= 1) m = fminf(m, __shfl_sync(0xFFFFFFFFu, m, lane ^ o));
    if (lane == 0) atomicMin(&sMin, __float_as_uint(m));  // positive floats: bits-ordered
    __syncthreads();

    const float thr = __uint_as_float(sMin) + DELTA;
    #pragma unroll
    for (int q = 0; q < 8; ++q)
        if (h[q] <= thr) { int p = atomicAdd(&cnt, 1); if (p < 256) grp[p] = tid * 8 + q; }
    __syncthreads();
    const int ng = min(cnt, 256);
    const int ncand = ng * 8;

    const float4* xr = (const float4*)(X + (size_t)b * DDIM);
    float4 xv[4];
    #pragma unroll
    for (int i = 0; i < 4; ++i) xv[i] = xr[i * 32 + lane];

    unsigned long long best = 0xFFFFFFFFFFFFFFFFULL;
    for (int ci = wid; ci < ncand; ci += 8) {
        const int k = grp[ci >> 3] * 8 + (ci & 7);
        const float4* wr = (const float4*)(gWt32 + (size_t)k * DDIM);
        float s = 0.f;
        #pragma unroll
        for (int i = 0; i < 4; ++i) {
            float4 w = wr[i * 32 + lane];
            s = fmaf(xv[i].x, w.x, s);
            s = fmaf(xv[i].y, w.y, s);
            s = fmaf(xv[i].z, w.z, s);
            s = fmaf(xv[i].w, w.w, s);
        }
        #pragma unroll
        for (int o = 16; o; o >>= 1) s += __shfl_xor_sync(0xFFFFFFFFu, s, o);
        if (lane == 0) {
            float d2 = g_r[b] + g_c[k] - 2.f * s;
            unsigned u = __float_as_uint(d2);
            u = (u & 0x80000000u) ? ~u : (u | 0x80000000u);
            unsigned long long key = ((unsigned long long)u << 32) | (unsigned)k;
            if (key < best) best = key;
        }
    }
    if (lane == 0) wbest[wid] = best;
    __syncthreads();

    if (tid == 0) {
        unsigned long long bb = 0xFFFFFFFFFFFFFFFFULL;
        #pragma unroll
        for (int w = 0; w < 8; ++w) if (wbest[w] < bb) bb = wbest[w];
        unsigned k = (unsigned)(bb & 0xFFFFFFFFu);
        unsigned u = (unsigned)(bb >> 32);
        u = (u & 0x80000000u) ? (u & 0x7FFFFFFFu) : ~u;
        float d2 = __uint_as_float(u);
        g_dist[b] = sqrtf(fmaxf(d2, 0.f));
        out[2 * b] = loc[2 * k];
        if (2 * b + 1 < out_size - 1) out[2 * b + 1] = loc[2 * k + 1];
    }
}

__global__ void loss_kernel(float* __restrict__ out, int out_size) {
    __shared__ float sh[1024];
    float local = 0.f;
    for (int b = threadIdx.x; b < B_ROWS; b += 1024) local += g_dist[b];
    sh[threadIdx.x] = local;
    __syncthreads();
    #pragma unroll
    for (int s = 512; s > 0; s >>= 1) {
        if (threadIdx.x < s) sh[threadIdx.x] += sh[threadIdx.x + s];
        __syncthreads();
    }
    if (threadIdx.x == 0) out[out_size - 1] = sh[0] / (float)B_ROWS;
}

// ---------------------------------------------------------------------------
extern "C" void kernel_launch(void* const* d_in, const int* in_sizes, int n_in,
                              void* d_out, int out_size) {
    const float* X = (const float*)d_in[0];  // (4096, 512)
    const float* W = (const float*)d_in[1];  // (512, 16384)
    const float* L = (const float*)d_in[2];  // (16384, 2)
    float* out = (float*)d_out;

    cudaFuncSetAttribute(gemm_kernel, cudaFuncAttributeMaxDynamicSharedMemorySize, SMEM_TOT);

    convx_kernel<<<(B_ROWS * DDIM + 255) / 256, 256>>>(X);
    transw_kernel<<<dim3(KN / 32, DDIM / 32), dim3(32, 8)>>>(W);
    col_stats_kernel<<<KN * 32 / 256, 256>>>();
    row_stats_kernel<<<B_ROWS, 128>>>(X);

    gemm_kernel<<<dim3(KN / 128, B_ROWS / 128), 256, SMEM_TOT>>>();

    refine_kernel<<<B_ROWS, 256>>>(X, L, out, out_size);
    loss_kernel<<<1, 1024>>>(out, out_size);
}